// round 15
// baseline (speedup 1.0000x reference)
#include <cuda_runtime.h>
#include <cuda_fp16.h>
#include <cstdint>

// Taylor causal attention, fp16 mma.sync m16n8k16 (fp32 accum).
// Fragment loads via ldmatrix.m8n8.x4 (plain row-major smem tiles).
// Persistent CTAs + dynamic LPT queue; 2-D warp tiling (4 row x 2 col groups);
// Q fragments re-loaded per s-step (kills register spills); K/V prepped.
// B=2,H=16,L=2048,D=64. Tile: 128 q-rows, k-tiles of 128.

#define L_SEQ 2048
#define DHEAD 64
#define NBH   32
#define BM    128
#define BN    128
#define QS    72     // Q/K smem row stride in halves (144B; ldmatrix conflict-free)
#define VTS   136    // Vt smem row stride in halves (272B; ldmatrix conflict-free)
#define OS    66     // O-partial reduction row stride (floats)
#define NTILES 512
#define SMEM_MAIN ((BM * QS + 2 * BN * QS + 2 * 64 * VTS) * 2)   // 90112 B

__device__ __align__(16) __half g_Kh[NBH * L_SEQ * DHEAD];  // row-major
__device__ __align__(16) __half g_Vth[NBH * DHEAD * L_SEQ]; // transposed [d][k]
__device__ int g_ctr;                                        // work-queue cursor

static __device__ __forceinline__ uint32_t packh2(float lo, float hi) {
    __half2 h = __floats2half2_rn(lo, hi);
    return *(uint32_t*)&h;
}
static __device__ __forceinline__ uint32_t smem_u32(const void* p) {
    uint32_t a;
    asm("{ .reg .u64 t; cvta.to.shared.u64 t, %1; cvt.u32.u64 %0, t; }" : "=r"(a) : "l"(p));
    return a;
}
static __device__ __forceinline__ void cp16(uint32_t s, const void* g) {
    asm volatile("cp.async.cg.shared.global [%0], [%1], 16;"
                 :: "r"(s), "l"(__cvta_generic_to_global(g)));
}
static __device__ __forceinline__ void cp_commit() {
    asm volatile("cp.async.commit_group;" ::: "memory");
}
static __device__ __forceinline__ void cp_wait0() {
    asm volatile("cp.async.wait_group 0;" ::: "memory");
}
static __device__ __forceinline__ void ldsm4(uint32_t& r0, uint32_t& r1,
                                             uint32_t& r2, uint32_t& r3, uint32_t a) {
    asm volatile("ldmatrix.sync.aligned.m8n8.x4.shared.b16 {%0,%1,%2,%3}, [%4];"
                 : "=r"(r0), "=r"(r1), "=r"(r2), "=r"(r3) : "r"(a));
}
static __device__ __forceinline__ void mma16(float* d,
        uint32_t a0, uint32_t a1, uint32_t a2, uint32_t a3,
        uint32_t b0, uint32_t b1) {
    asm volatile(
        "mma.sync.aligned.m16n8k16.row.col.f32.f16.f16.f32 "
        "{%0,%1,%2,%3}, {%4,%5,%6,%7}, {%8,%9}, {%0,%1,%2,%3};"
        : "+f"(d[0]), "+f"(d[1]), "+f"(d[2]), "+f"(d[3])
        : "r"(a0), "r"(a1), "r"(a2), "r"(a3), "r"(b0), "r"(b1));
}

// ---- prep: y=0 -> K fp16 convert (row-major); y=1 -> V transpose ----
__global__ void __launch_bounds__(256)
prep_all(const float* __restrict__ K, const float* __restrict__ V)
{
    if (blockIdx.x == 0 && blockIdx.y == 0 && threadIdx.x == 0) g_ctr = 0;

    if (blockIdx.y == 0) {
        const int g   = blockIdx.x * 256 + threadIdx.x;   // one (row, 16-col blk)
        const size_t off = (size_t)(g >> 2) * DHEAD + ((g & 3) << 4);

        float4 f0 = *(const float4*)(K + off);
        float4 f1 = *(const float4*)(K + off + 4);
        float4 f2 = *(const float4*)(K + off + 8);
        float4 f3 = *(const float4*)(K + off + 12);
        uint4 a, b;
        a.x = packh2(f0.x, f0.y);  a.y = packh2(f0.z, f0.w);
        a.z = packh2(f1.x, f1.y);  a.w = packh2(f1.z, f1.w);
        b.x = packh2(f2.x, f2.y);  b.y = packh2(f2.z, f2.w);
        b.z = packh2(f3.x, f3.y);  b.w = packh2(f3.z, f3.w);
        *(uint4*)(g_Kh + off)     = a;
        *(uint4*)(g_Kh + off + 8) = b;
    } else {
        __shared__ float ts[64][68];
        const int tid = threadIdx.x;
        const int kt0 = (blockIdx.x & 31) * 64;
        const int bh  = blockIdx.x >> 5;
        const float* vsrc = V + (size_t)bh * L_SEQ * DHEAD;
        __half* vdst = g_Vth + (size_t)bh * DHEAD * L_SEQ;

        #pragma unroll
        for (int i = 0; i < 4; ++i) {
            const int idx = tid + 256 * i;
            const int row = idx >> 4, c4 = (idx & 15) << 2;
            *(float4*)&ts[row][c4] =
                *(const float4*)(vsrc + (size_t)(kt0 + row) * DHEAD + c4);
        }
        __syncthreads();

        const int d  = tid >> 2;
        const int kb = (tid & 3) << 4;
        uint4 a, b;
        a.x = packh2(ts[kb + 0][d],  ts[kb + 1][d]);
        a.y = packh2(ts[kb + 2][d],  ts[kb + 3][d]);
        a.z = packh2(ts[kb + 4][d],  ts[kb + 5][d]);
        a.w = packh2(ts[kb + 6][d],  ts[kb + 7][d]);
        b.x = packh2(ts[kb + 8][d],  ts[kb + 9][d]);
        b.y = packh2(ts[kb + 10][d], ts[kb + 11][d]);
        b.z = packh2(ts[kb + 12][d], ts[kb + 13][d]);
        b.w = packh2(ts[kb + 14][d], ts[kb + 15][d]);
        __half* dst = vdst + (size_t)d * L_SEQ + kt0 + kb;
        *(uint4*)dst       = a;
        *(uint4*)(dst + 8) = b;
    }
}

// ---- one k-tile of compute for one warp (4 chunks of 16 cols) ----
// kBase/vBase: smem byte addr incl. per-lane ldmatrix offset for this buffer.
// qAddr0/qAddr1: per-warp Q fragment base addresses (mi = 0, 1).
template<bool DIAG>
static __device__ __forceinline__ void tile_step(
    uint32_t kBase, uint32_t vBase, uint32_t qAddr0, uint32_t qAddr1,
    float (&oacc)[2][8][4], float (&zr)[2][2],
    int colw, int rbase, int c)
{
    #pragma unroll
    for (int ch = 0; ch < 4; ++ch) {
        const int cb0 = colw + 16 * ch;           // chunk column base (local)
        if (DIAG && cb0 > rbase + 31) break;      // fully above all warp rows
        const bool t1 = !DIAG || (cb0 + 8 <= rbase + 31);

        // ---- MMA1: S chunk (32 rows x 16 cols); Q+K frags via ldmatrix ----
        float sacc[2][2][4];
        #pragma unroll
        for (int mi = 0; mi < 2; ++mi)
            #pragma unroll
            for (int t = 0; t < 2; ++t)
                #pragma unroll
                for (int jj = 0; jj < 4; ++jj) sacc[mi][t][jj] = 0.0f;

        const uint32_t kCh = kBase + (uint32_t)(cb0 * QS) * 2;
        #pragma unroll
        for (int s = 0; s < 4; ++s) {
            uint32_t q0, q1, q2, q3, p0, p1, p2, p3;
            ldsm4(q0, q1, q2, q3, qAddr0 + 32u * s);
            ldsm4(p0, p1, p2, p3, qAddr1 + 32u * s);
            uint32_t k0, k1, k2, k3;
            ldsm4(k0, k1, k2, k3, kCh + 32u * s);
            mma16(sacc[0][0], q0, q1, q2, q3, k0, k1);
            mma16(sacc[1][0], p0, p1, p2, p3, k0, k1);
            if (t1) {
                mma16(sacc[0][1], q0, q1, q2, q3, k2, k3);
                mma16(sacc[1][1], p0, p1, p2, p3, k2, k3);
            }
        }

        // ---- epilogue: f(s), mask, z, pack ----
        uint32_t pr[2][2][2];
        #pragma unroll
        for (int mi = 0; mi < 2; ++mi)
            #pragma unroll
            for (int t = 0; t < 2; ++t) { pr[mi][t][0] = 0u; pr[mi][t][1] = 0u; }
        #pragma unroll
        for (int mi = 0; mi < 2; ++mi) {
            const int r0 = rbase + 16 * mi + ((threadIdx.x & 31) >> 2);
            #pragma unroll
            for (int t = 0; t < 2; ++t) {
                if (DIAG && t == 1 && !t1) continue;
                const int cb = cb0 + 8 * t + 2 * c;   // local col of p0/p2
                float s0 = sacc[mi][t][0], s1 = sacc[mi][t][1];
                float s2 = sacc[mi][t][2], s3 = sacc[mi][t][3];
                float p0 = fmaf(fmaf(0.5f, s0, 1.0f), s0, 1.0f);
                float p1 = fmaf(fmaf(0.5f, s1, 1.0f), s1, 1.0f);
                float p2 = fmaf(fmaf(0.5f, s2, 1.0f), s2, 1.0f);
                float p3 = fmaf(fmaf(0.5f, s3, 1.0f), s3, 1.0f);
                if (DIAG) {
                    if (cb     > r0)     p0 = 0.0f;
                    if (cb + 1 > r0)     p1 = 0.0f;
                    if (cb     > r0 + 8) p2 = 0.0f;
                    if (cb + 1 > r0 + 8) p3 = 0.0f;
                }
                zr[mi][0] += p0 + p1;
                zr[mi][1] += p2 + p3;
                pr[mi][t][0] = packh2(p0, p1);
                pr[mi][t][1] = packh2(p2, p3);
            }
        }

        // ---- MMA2: O += P @ V ; V frags via ldmatrix; A-frag = pr in-lane ----
        const uint32_t vCh = vBase + (uint32_t)cb0 * 2;
        #pragma unroll
        for (int tp = 0; tp < 4; ++tp) {
            uint32_t v0, v1, v2, v3;
            ldsm4(v0, v1, v2, v3, vCh + (uint32_t)(32 * VTS) * tp);
            mma16(oacc[0][2 * tp],     pr[0][0][0], pr[0][0][1], pr[0][1][0], pr[0][1][1], v0, v1);
            mma16(oacc[0][2 * tp + 1], pr[0][0][0], pr[0][0][1], pr[0][1][0], pr[0][1][1], v2, v3);
            mma16(oacc[1][2 * tp],     pr[1][0][0], pr[1][0][1], pr[1][1][0], pr[1][1][1], v0, v1);
            mma16(oacc[1][2 * tp + 1], pr[1][0][0], pr[1][0][1], pr[1][1][0], pr[1][1][1], v2, v3);
        }
    }
}

// ---- main kernel: persistent CTAs over a dynamic LPT work list ----
__global__ void __launch_bounds__(256, 2)
taylor_attn_h(const float* __restrict__ Q, float* __restrict__ O)
{
    extern __shared__ __half smh[];
    __half* Qs = smh;                      // [128][72]
    __half* Kb = Qs + BM * QS;             // [2][128][72]
    __half* Vb = Kb + 2 * BN * QS;         // [2][64][136]
    int* wptr  = (int*)((char*)smh + SMEM_MAIN);
    const uint32_t sKb = smem_u32(Kb);
    const uint32_t sVb = smem_u32(Vb);
    const uint32_t sQs = smem_u32(Qs);

    const int tid  = threadIdx.x;
    const int wid  = tid >> 5;
    const int lane = tid & 31;
    const int grp  = lane >> 2;
    const int c    = lane & 3;
    const int mw   = wid & 3;              // row group (32 rows)
    const int nw   = wid >> 2;             // col group (64 cols)
    const int rbase = 32 * mw;
    const int colw  = 64 * nw;

    // per-lane ldmatrix offsets (halves)
    const int lo8 = lane & 7;
    const int selA = (lane >> 3) & 1;
    const int selB = (lane >> 4) & 1;
    const int kLane = (selB * 8 + lo8) * QS + selA * 8;
    const int vLane = (selB * 8 + lo8) * VTS + selA * 8;
    const int qLane = (selA * 8 + lo8) * QS + selB * 8;
    // Q fragment base addresses (Q tile is single-buffered)
    const uint32_t qAddr0 = sQs + (uint32_t)(qLane + rbase * QS) * 2;
    const uint32_t qAddr1 = sQs + (uint32_t)(qLane + (rbase + 16) * QS) * 2;

    for (;;) {
        if (tid == 0) *wptr = atomicAdd(&g_ctr, 1);
        __syncthreads();
        const int widx = *wptr;
        if (widx >= NTILES) break;

        const int qt = (L_SEQ / BM) - 1 - (widx >> 5);   // LPT: big first
        const int bh = widx & 31;
        const int qbase = qt * BM;

        const float*  Qg = Q + (size_t)bh * L_SEQ * DHEAD + (size_t)qbase * DHEAD;
        const __half* Kg = g_Kh + (size_t)bh * L_SEQ * DHEAD;
        const __half* Vg = g_Vth + (size_t)bh * DHEAD * L_SEQ;

        // ---- prologue: K/V tile 0 via cp.async; Q fp32 -> fp16 convert ----
        #pragma unroll
        for (int i = 0; i < 4; ++i) {
            const int idx = tid + 256 * i;
            const int row = idx >> 3, ch = idx & 7;
            cp16(sKb + (uint32_t)(row * QS + ch * 8) * 2,
                 Kg + (size_t)row * DHEAD + ch * 8);
        }
        #pragma unroll
        for (int i = 0; i < 4; ++i) {
            const int idx = tid + 256 * i;
            const int row = idx >> 4, ch = idx & 15;
            cp16(sVb + (uint32_t)(row * VTS + ch * 8) * 2,
                 Vg + (size_t)row * L_SEQ + ch * 8);
        }
        cp_commit();

        // Q: 512 items of 16 floats each -> 16 halves (scaled by 1/8)
        #pragma unroll
        for (int i = 0; i < 2; ++i) {
            const int item = tid + 256 * i;
            const int row  = item >> 2;
            const int c16  = (item & 3) << 4;
            const float* src = Qg + (size_t)row * DHEAD + c16;
            float4 f0 = *(const float4*)(src);
            float4 f1 = *(const float4*)(src + 4);
            float4 f2 = *(const float4*)(src + 8);
            float4 f3 = *(const float4*)(src + 12);
            uint4 a, b;
            a.x = packh2(f0.x * 0.125f, f0.y * 0.125f);
            a.y = packh2(f0.z * 0.125f, f0.w * 0.125f);
            a.z = packh2(f1.x * 0.125f, f1.y * 0.125f);
            a.w = packh2(f1.z * 0.125f, f1.w * 0.125f);
            b.x = packh2(f2.x * 0.125f, f2.y * 0.125f);
            b.y = packh2(f2.z * 0.125f, f2.w * 0.125f);
            b.z = packh2(f3.x * 0.125f, f3.y * 0.125f);
            b.w = packh2(f3.z * 0.125f, f3.w * 0.125f);
            *(uint4*)(Qs + row * QS + c16)     = a;
            *(uint4*)(Qs + row * QS + c16 + 8) = b;
        }
        cp_wait0();
        __syncthreads();

        float oacc[2][8][4];
        #pragma unroll
        for (int mi = 0; mi < 2; ++mi)
            #pragma unroll
            for (int t = 0; t < 8; ++t)
                #pragma unroll
                for (int j = 0; j < 4; ++j) oacc[mi][t][j] = 0.0f;
        float zr[2][2] = {};

        for (int j = 0; j <= qt; ++j) {
            const int buf = j & 1;

            if (j < qt) {   // prefetch tile j+1 into the other buffer
                const int nb = buf ^ 1;
                const int kb1 = (j + 1) * BN;
                const uint32_t dK = sKb + (uint32_t)(nb * BN * QS) * 2;
                const uint32_t dV = sVb + (uint32_t)(nb * 64 * VTS) * 2;
                #pragma unroll
                for (int i = 0; i < 4; ++i) {
                    const int idx = tid + 256 * i;
                    const int rowk = idx >> 3, chk = idx & 7;
                    cp16(dK + (uint32_t)(rowk * QS + chk * 8) * 2,
                         Kg + (size_t)(kb1 + rowk) * DHEAD + chk * 8);
                    const int rowv = idx >> 4, chv = idx & 15;
                    cp16(dV + (uint32_t)(rowv * VTS + chv * 8) * 2,
                         Vg + (size_t)rowv * L_SEQ + kb1 + chv * 8);
                }
                cp_commit();
            }

            const uint32_t kBase = sKb + (uint32_t)(buf * BN * QS) * 2
                                 + (uint32_t)kLane * 2;
            const uint32_t vBase = sVb + (uint32_t)(buf * 64 * VTS) * 2
                                 + (uint32_t)vLane * 2;
            if (j == qt)
                tile_step<true >(kBase, vBase, qAddr0, qAddr1, oacc, zr, colw, rbase, c);
            else
                tile_step<false>(kBase, vBase, qAddr0, qAddr1, oacc, zr, colw, rbase, c);

            if (j < qt) cp_wait0();
            __syncthreads();   // buf free + next tile visible to all warps
        }

        // ---- z lane-reduce over the 4 c-lanes ----
        #pragma unroll
        for (int mi = 0; mi < 2; ++mi) {
            zr[mi][0] += __shfl_xor_sync(0xffffffffu, zr[mi][0], 1);
            zr[mi][0] += __shfl_xor_sync(0xffffffffu, zr[mi][0], 2);
            zr[mi][1] += __shfl_xor_sync(0xffffffffu, zr[mi][1], 1);
            zr[mi][1] += __shfl_xor_sync(0xffffffffu, zr[mi][1], 2);
        }

        // ---- cross-col-group reduction via smem (reuse K/V buffer space) ----
        float* Osum = (float*)(smh + BM * QS);
        float* Zsum = (float*)(smh + BM * QS + 2 * BN * QS);

        if (nw == 1) {
            float* base = Osum + mw * 32 * OS;
            #pragma unroll
            for (int mi = 0; mi < 2; ++mi) {
                const int r0 = 16 * mi + grp;
                #pragma unroll
                for (int tn = 0; tn < 8; ++tn) {
                    *(float2*)(base + r0 * OS + 8 * tn + 2 * c) =
                        make_float2(oacc[mi][tn][0], oacc[mi][tn][1]);
                    *(float2*)(base + (r0 + 8) * OS + 8 * tn + 2 * c) =
                        make_float2(oacc[mi][tn][2], oacc[mi][tn][3]);
                }
                if (c == 0) {
                    Zsum[rbase + 16 * mi + grp]     = zr[mi][0];
                    Zsum[rbase + 16 * mi + grp + 8] = zr[mi][1];
                }
            }
        }
        __syncthreads();

        if (nw == 0) {
            float* base = Osum + mw * 32 * OS;
            #pragma unroll
            for (int mi = 0; mi < 2; ++mi) {
                const int r0 = 16 * mi + grp;
                const float z0 = zr[mi][0] + Zsum[rbase + r0];
                const float z1 = zr[mi][1] + Zsum[rbase + r0 + 8];
                const float inv0 = 1.0f / (z0 + 1e-6f);
                const float inv1 = 1.0f / (z1 + 1e-6f);
                float* ob0 = O + (size_t)bh * L_SEQ * DHEAD
                           + (size_t)(qbase + rbase + r0) * DHEAD + 2 * c;
                float* ob1 = ob0 + 8 * DHEAD;
                #pragma unroll
                for (int tn = 0; tn < 8; ++tn) {
                    const float2 s0 = *(const float2*)(base + r0 * OS + 8 * tn + 2 * c);
                    const float2 s1 = *(const float2*)(base + (r0 + 8) * OS + 8 * tn + 2 * c);
                    float2 w0, w1;
                    w0.x = (oacc[mi][tn][0] + s0.x) * inv0;
                    w0.y = (oacc[mi][tn][1] + s0.y) * inv0;
                    w1.x = (oacc[mi][tn][2] + s1.x) * inv1;
                    w1.y = (oacc[mi][tn][3] + s1.y) * inv1;
                    *(float2*)(ob0 + 8 * tn) = w0;
                    *(float2*)(ob1 + 8 * tn) = w1;
                }
            }
        }
        __syncthreads();   // Osum readers done before next tile's prologue
    }
}

extern "C" void kernel_launch(void* const* d_in, const int* in_sizes, int n_in,
                              void* d_out, int out_size) {
    (void)in_sizes; (void)n_in; (void)out_size;
    const float* q = (const float*)d_in[0];
    const float* k = (const float*)d_in[1];
    const float* v = (const float*)d_in[2];
    float* o = (float*)d_out;

    const int smem_bytes = SMEM_MAIN + 16;
    static bool configured = false;
    if (!configured) {
        cudaFuncSetAttribute(taylor_attn_h,
                             cudaFuncAttributeMaxDynamicSharedMemorySize, smem_bytes);
        configured = true;
    }

    prep_all<<<dim3(1024, 2), 256>>>(k, v);

    taylor_attn_h<<<304, 256, smem_bytes>>>(q, o);   // persistent: 2 CTAs x 152 SMs
}

// round 16
// speedup vs baseline: 1.0308x; 1.0308x over previous
#include <cuda_runtime.h>
#include <cuda_fp16.h>
#include <cstdint>

// Taylor causal attention, fp16 mma.sync m16n8k16 (fp32 accum).
// Fragment loads via ldmatrix.m8n8.x4 (plain row-major smem tiles).
// Persistent CTAs + dynamic LPT queue; 2-D warp tiling (4 row x 2 col groups);
// Q fragments register-hoisted; per-warp ROTATED chunk order to de-correlate
// warp phases (fill tensor-pipe gaps); Q converted in-prologue; K/V prepped.
// B=2,H=16,L=2048,D=64. Tile: 128 q-rows, k-tiles of 128.

#define L_SEQ 2048
#define DHEAD 64
#define NBH   32
#define BM    128
#define BN    128
#define QS    72     // Q/K smem row stride in halves (144B; ldmatrix conflict-free)
#define VTS   136    // Vt smem row stride in halves (272B; ldmatrix conflict-free)
#define OS    66     // O-partial reduction row stride (floats)
#define NTILES 512
#define SMEM_MAIN ((BM * QS + 2 * BN * QS + 2 * 64 * VTS) * 2)   // 90112 B

__device__ __align__(16) __half g_Kh[NBH * L_SEQ * DHEAD];  // row-major
__device__ __align__(16) __half g_Vth[NBH * DHEAD * L_SEQ]; // transposed [d][k]
__device__ int g_ctr;                                        // work-queue cursor

static __device__ __forceinline__ uint32_t packh2(float lo, float hi) {
    __half2 h = __floats2half2_rn(lo, hi);
    return *(uint32_t*)&h;
}
static __device__ __forceinline__ uint32_t smem_u32(const void* p) {
    uint32_t a;
    asm("{ .reg .u64 t; cvta.to.shared.u64 t, %1; cvt.u32.u64 %0, t; }" : "=r"(a) : "l"(p));
    return a;
}
static __device__ __forceinline__ void cp16(uint32_t s, const void* g) {
    asm volatile("cp.async.cg.shared.global [%0], [%1], 16;"
                 :: "r"(s), "l"(__cvta_generic_to_global(g)));
}
static __device__ __forceinline__ void cp_commit() {
    asm volatile("cp.async.commit_group;" ::: "memory");
}
static __device__ __forceinline__ void cp_wait0() {
    asm volatile("cp.async.wait_group 0;" ::: "memory");
}
static __device__ __forceinline__ void ldsm4(uint32_t& r0, uint32_t& r1,
                                             uint32_t& r2, uint32_t& r3, uint32_t a) {
    asm volatile("ldmatrix.sync.aligned.m8n8.x4.shared.b16 {%0,%1,%2,%3}, [%4];"
                 : "=r"(r0), "=r"(r1), "=r"(r2), "=r"(r3) : "r"(a));
}
static __device__ __forceinline__ void mma16(float* d,
        uint32_t a0, uint32_t a1, uint32_t a2, uint32_t a3,
        uint32_t b0, uint32_t b1) {
    asm volatile(
        "mma.sync.aligned.m16n8k16.row.col.f32.f16.f16.f32 "
        "{%0,%1,%2,%3}, {%4,%5,%6,%7}, {%8,%9}, {%0,%1,%2,%3};"
        : "+f"(d[0]), "+f"(d[1]), "+f"(d[2]), "+f"(d[3])
        : "r"(a0), "r"(a1), "r"(a2), "r"(a3), "r"(b0), "r"(b1));
}

// ---- prep: y=0 -> K fp16 convert (row-major); y=1 -> V transpose ----
__global__ void __launch_bounds__(256)
prep_all(const float* __restrict__ K, const float* __restrict__ V)
{
    if (blockIdx.x == 0 && blockIdx.y == 0 && threadIdx.x == 0) g_ctr = 0;

    if (blockIdx.y == 0) {
        const int g   = blockIdx.x * 256 + threadIdx.x;   // one (row, 16-col blk)
        const size_t off = (size_t)(g >> 2) * DHEAD + ((g & 3) << 4);

        float4 f0 = *(const float4*)(K + off);
        float4 f1 = *(const float4*)(K + off + 4);
        float4 f2 = *(const float4*)(K + off + 8);
        float4 f3 = *(const float4*)(K + off + 12);
        uint4 a, b;
        a.x = packh2(f0.x, f0.y);  a.y = packh2(f0.z, f0.w);
        a.z = packh2(f1.x, f1.y);  a.w = packh2(f1.z, f1.w);
        b.x = packh2(f2.x, f2.y);  b.y = packh2(f2.z, f2.w);
        b.z = packh2(f3.x, f3.y);  b.w = packh2(f3.z, f3.w);
        *(uint4*)(g_Kh + off)     = a;
        *(uint4*)(g_Kh + off + 8) = b;
    } else {
        __shared__ float ts[64][68];
        const int tid = threadIdx.x;
        const int kt0 = (blockIdx.x & 31) * 64;
        const int bh  = blockIdx.x >> 5;
        const float* vsrc = V + (size_t)bh * L_SEQ * DHEAD;
        __half* vdst = g_Vth + (size_t)bh * DHEAD * L_SEQ;

        #pragma unroll
        for (int i = 0; i < 4; ++i) {
            const int idx = tid + 256 * i;
            const int row = idx >> 4, c4 = (idx & 15) << 2;
            *(float4*)&ts[row][c4] =
                *(const float4*)(vsrc + (size_t)(kt0 + row) * DHEAD + c4);
        }
        __syncthreads();

        const int d  = tid >> 2;
        const int kb = (tid & 3) << 4;
        uint4 a, b;
        a.x = packh2(ts[kb + 0][d],  ts[kb + 1][d]);
        a.y = packh2(ts[kb + 2][d],  ts[kb + 3][d]);
        a.z = packh2(ts[kb + 4][d],  ts[kb + 5][d]);
        a.w = packh2(ts[kb + 6][d],  ts[kb + 7][d]);
        b.x = packh2(ts[kb + 8][d],  ts[kb + 9][d]);
        b.y = packh2(ts[kb + 10][d], ts[kb + 11][d]);
        b.z = packh2(ts[kb + 12][d], ts[kb + 13][d]);
        b.w = packh2(ts[kb + 14][d], ts[kb + 15][d]);
        __half* dst = vdst + (size_t)d * L_SEQ + kt0 + kb;
        *(uint4*)dst       = a;
        *(uint4*)(dst + 8) = b;
    }
}

// ---- one chunk (16 cols) of MMA1 + epilogue + MMA2 for one warp ----
template<bool DIAG>
static __device__ __forceinline__ void chunk_step(
    int cb0, uint32_t kBase, uint32_t vBase,
    const uint32_t (&qf)[2][4][4],
    float (&oacc)[2][8][4], float (&zr)[2][2],
    int rbase, int c, bool t1)
{
    // ---- MMA1: S chunk (32 rows x 16 cols); K frags via ldmatrix ----
    float sacc[2][2][4];
    #pragma unroll
    for (int mi = 0; mi < 2; ++mi)
        #pragma unroll
        for (int t = 0; t < 2; ++t)
            #pragma unroll
            for (int jj = 0; jj < 4; ++jj) sacc[mi][t][jj] = 0.0f;

    const uint32_t kCh = kBase + (uint32_t)(cb0 * QS) * 2;
    #pragma unroll
    for (int s = 0; s < 4; ++s) {
        uint32_t k0, k1, k2, k3;
        ldsm4(k0, k1, k2, k3, kCh + 32u * s);
        mma16(sacc[0][0], qf[0][s][0], qf[0][s][1], qf[0][s][2], qf[0][s][3], k0, k1);
        mma16(sacc[1][0], qf[1][s][0], qf[1][s][1], qf[1][s][2], qf[1][s][3], k0, k1);
        if (t1) {
            mma16(sacc[0][1], qf[0][s][0], qf[0][s][1], qf[0][s][2], qf[0][s][3], k2, k3);
            mma16(sacc[1][1], qf[1][s][0], qf[1][s][1], qf[1][s][2], qf[1][s][3], k2, k3);
        }
    }

    // ---- epilogue: f(s), mask, z, pack ----
    uint32_t pr[2][2][2];
    #pragma unroll
    for (int mi = 0; mi < 2; ++mi)
        #pragma unroll
        for (int t = 0; t < 2; ++t) { pr[mi][t][0] = 0u; pr[mi][t][1] = 0u; }
    #pragma unroll
    for (int mi = 0; mi < 2; ++mi) {
        const int r0 = rbase + 16 * mi + ((threadIdx.x & 31) >> 2);
        #pragma unroll
        for (int t = 0; t < 2; ++t) {
            if (DIAG && t == 1 && !t1) continue;
            const int cb = cb0 + 8 * t + 2 * c;   // local col of p0/p2
            float s0 = sacc[mi][t][0], s1 = sacc[mi][t][1];
            float s2 = sacc[mi][t][2], s3 = sacc[mi][t][3];
            float p0 = fmaf(fmaf(0.5f, s0, 1.0f), s0, 1.0f);
            float p1 = fmaf(fmaf(0.5f, s1, 1.0f), s1, 1.0f);
            float p2 = fmaf(fmaf(0.5f, s2, 1.0f), s2, 1.0f);
            float p3 = fmaf(fmaf(0.5f, s3, 1.0f), s3, 1.0f);
            if (DIAG) {
                if (cb     > r0)     p0 = 0.0f;
                if (cb + 1 > r0)     p1 = 0.0f;
                if (cb     > r0 + 8) p2 = 0.0f;
                if (cb + 1 > r0 + 8) p3 = 0.0f;
            }
            zr[mi][0] += p0 + p1;
            zr[mi][1] += p2 + p3;
            pr[mi][t][0] = packh2(p0, p1);
            pr[mi][t][1] = packh2(p2, p3);
        }
    }

    // ---- MMA2: O += P @ V ; V frags via ldmatrix; A-frag = pr in-lane ----
    const uint32_t vCh = vBase + (uint32_t)cb0 * 2;
    #pragma unroll
    for (int tp = 0; tp < 4; ++tp) {
        uint32_t v0, v1, v2, v3;
        ldsm4(v0, v1, v2, v3, vCh + (uint32_t)(32 * VTS) * tp);
        mma16(oacc[0][2 * tp],     pr[0][0][0], pr[0][0][1], pr[0][1][0], pr[0][1][1], v0, v1);
        mma16(oacc[0][2 * tp + 1], pr[0][0][0], pr[0][0][1], pr[0][1][0], pr[0][1][1], v2, v3);
        mma16(oacc[1][2 * tp],     pr[1][0][0], pr[1][0][1], pr[1][1][0], pr[1][1][1], v0, v1);
        mma16(oacc[1][2 * tp + 1], pr[1][0][0], pr[1][0][1], pr[1][1][0], pr[1][1][1], v2, v3);
    }
}

// ---- one k-tile of compute for one warp (4 chunks of 16 cols) ----
// Non-diag: chunks processed in per-warp ROTATED order (start = rot) so the
// 8 warps' epilogue phases interleave instead of colliding.
template<bool DIAG>
static __device__ __forceinline__ void tile_step(
    uint32_t kBase, uint32_t vBase,
    const uint32_t (&qf)[2][4][4],
    float (&oacc)[2][8][4], float (&zr)[2][2],
    int colw, int rbase, int c, int rot)
{
    if (DIAG) {
        #pragma unroll
        for (int ch = 0; ch < 4; ++ch) {
            const int cb0 = colw + 16 * ch;
            if (cb0 > rbase + 31) break;            // fully above all warp rows
            const bool t1 = (cb0 + 8 <= rbase + 31);
            chunk_step<true>(cb0, kBase, vBase, qf, oacc, zr, rbase, c, t1);
        }
    } else {
        #pragma unroll
        for (int i = 0; i < 4; ++i) {
            const int ch = (rot + i) & 3;
            const int cb0 = colw + 16 * ch;
            chunk_step<false>(cb0, kBase, vBase, qf, oacc, zr, rbase, c, true);
        }
    }
}

// ---- main kernel: persistent CTAs over a dynamic LPT work list ----
__global__ void __launch_bounds__(256, 2)
taylor_attn_h(const float* __restrict__ Q, float* __restrict__ O)
{
    extern __shared__ __half smh[];
    __half* Qs = smh;                      // [128][72]
    __half* Kb = Qs + BM * QS;             // [2][128][72]
    __half* Vb = Kb + 2 * BN * QS;         // [2][64][136]
    int* wptr  = (int*)((char*)smh + SMEM_MAIN);
    const uint32_t sKb = smem_u32(Kb);
    const uint32_t sVb = smem_u32(Vb);
    const uint32_t sQs = smem_u32(Qs);

    const int tid  = threadIdx.x;
    const int wid  = tid >> 5;
    const int lane = tid & 31;
    const int grp  = lane >> 2;
    const int c    = lane & 3;
    const int mw   = wid & 3;              // row group (32 rows)
    const int nw   = wid >> 2;             // col group (64 cols)
    const int rbase = 32 * mw;
    const int colw  = 64 * nw;
    const int rot   = wid & 3;             // per-warp chunk rotation

    // per-lane ldmatrix offsets (halves)
    const int lo8 = lane & 7;
    const int selA = (lane >> 3) & 1;
    const int selB = (lane >> 4) & 1;
    const int kLane = (selB * 8 + lo8) * QS + selA * 8;
    const int vLane = (selB * 8 + lo8) * VTS + selA * 8;
    const int qLane = (selA * 8 + lo8) * QS + selB * 8;

    for (;;) {
        if (tid == 0) *wptr = atomicAdd(&g_ctr, 1);
        __syncthreads();
        const int widx = *wptr;
        if (widx >= NTILES) break;

        const int qt = (L_SEQ / BM) - 1 - (widx >> 5);   // LPT: big first
        const int bh = widx & 31;
        const int qbase = qt * BM;

        const float*  Qg = Q + (size_t)bh * L_SEQ * DHEAD + (size_t)qbase * DHEAD;
        const __half* Kg = g_Kh + (size_t)bh * L_SEQ * DHEAD;
        const __half* Vg = g_Vth + (size_t)bh * DHEAD * L_SEQ;

        // ---- prologue: K/V tile 0 via cp.async; Q fp32 -> fp16 convert ----
        #pragma unroll
        for (int i = 0; i < 4; ++i) {
            const int idx = tid + 256 * i;
            const int row = idx >> 3, ch = idx & 7;
            cp16(sKb + (uint32_t)(row * QS + ch * 8) * 2,
                 Kg + (size_t)row * DHEAD + ch * 8);
        }
        #pragma unroll
        for (int i = 0; i < 4; ++i) {
            const int idx = tid + 256 * i;
            const int row = idx >> 4, ch = idx & 15;
            cp16(sVb + (uint32_t)(row * VTS + ch * 8) * 2,
                 Vg + (size_t)row * L_SEQ + ch * 8);
        }
        cp_commit();

        // Q: 512 items of 16 floats each -> 16 halves (scaled by 1/8)
        #pragma unroll
        for (int i = 0; i < 2; ++i) {
            const int item = tid + 256 * i;
            const int row  = item >> 2;
            const int c16  = (item & 3) << 4;
            const float* src = Qg + (size_t)row * DHEAD + c16;
            float4 f0 = *(const float4*)(src);
            float4 f1 = *(const float4*)(src + 4);
            float4 f2 = *(const float4*)(src + 8);
            float4 f3 = *(const float4*)(src + 12);
            uint4 a, b;
            a.x = packh2(f0.x * 0.125f, f0.y * 0.125f);
            a.y = packh2(f0.z * 0.125f, f0.w * 0.125f);
            a.z = packh2(f1.x * 0.125f, f1.y * 0.125f);
            a.w = packh2(f1.z * 0.125f, f1.w * 0.125f);
            b.x = packh2(f2.x * 0.125f, f2.y * 0.125f);
            b.y = packh2(f2.z * 0.125f, f2.w * 0.125f);
            b.z = packh2(f3.x * 0.125f, f3.y * 0.125f);
            b.w = packh2(f3.z * 0.125f, f3.w * 0.125f);
            *(uint4*)(Qs + row * QS + c16)     = a;
            *(uint4*)(Qs + row * QS + c16 + 8) = b;
        }
        cp_wait0();
        __syncthreads();

        // ---- Q fragments -> registers for the whole k-loop (ldmatrix) ----
        uint32_t qf[2][4][4];
        #pragma unroll
        for (int mi = 0; mi < 2; ++mi)
            #pragma unroll
            for (int s = 0; s < 4; ++s)
                ldsm4(qf[mi][s][0], qf[mi][s][1], qf[mi][s][2], qf[mi][s][3],
                      sQs + (uint32_t)(qLane + (rbase + 16 * mi) * QS + 16 * s) * 2);

        float oacc[2][8][4];
        #pragma unroll
        for (int mi = 0; mi < 2; ++mi)
            #pragma unroll
            for (int t = 0; t < 8; ++t)
                #pragma unroll
                for (int j = 0; j < 4; ++j) oacc[mi][t][j] = 0.0f;
        float zr[2][2] = {};

        for (int j = 0; j <= qt; ++j) {
            const int buf = j & 1;

            if (j < qt) {   // prefetch tile j+1 into the other buffer
                const int nb = buf ^ 1;
                const int kb1 = (j + 1) * BN;
                const uint32_t dK = sKb + (uint32_t)(nb * BN * QS) * 2;
                const uint32_t dV = sVb + (uint32_t)(nb * 64 * VTS) * 2;
                #pragma unroll
                for (int i = 0; i < 4; ++i) {
                    const int idx = tid + 256 * i;
                    const int rowk = idx >> 3, chk = idx & 7;
                    cp16(dK + (uint32_t)(rowk * QS + chk * 8) * 2,
                         Kg + (size_t)(kb1 + rowk) * DHEAD + chk * 8);
                    const int rowv = idx >> 4, chv = idx & 15;
                    cp16(dV + (uint32_t)(rowv * VTS + chv * 8) * 2,
                         Vg + (size_t)rowv * L_SEQ + kb1 + chv * 8);
                }
                cp_commit();
            }

            const uint32_t kBase = sKb + (uint32_t)(buf * BN * QS) * 2
                                 + (uint32_t)kLane * 2;
            const uint32_t vBase = sVb + (uint32_t)(buf * 64 * VTS) * 2
                                 + (uint32_t)vLane * 2;
            if (j == qt)
                tile_step<true >(kBase, vBase, qf, oacc, zr, colw, rbase, c, rot);
            else
                tile_step<false>(kBase, vBase, qf, oacc, zr, colw, rbase, c, rot);

            if (j < qt) cp_wait0();
            __syncthreads();   // buf free + next tile visible to all warps
        }

        // ---- z lane-reduce over the 4 c-lanes ----
        #pragma unroll
        for (int mi = 0; mi < 2; ++mi) {
            zr[mi][0] += __shfl_xor_sync(0xffffffffu, zr[mi][0], 1);
            zr[mi][0] += __shfl_xor_sync(0xffffffffu, zr[mi][0], 2);
            zr[mi][1] += __shfl_xor_sync(0xffffffffu, zr[mi][1], 1);
            zr[mi][1] += __shfl_xor_sync(0xffffffffu, zr[mi][1], 2);
        }

        // ---- cross-col-group reduction via smem (reuse K/V buffer space) ----
        float* Osum = (float*)(smh + BM * QS);
        float* Zsum = (float*)(smh + BM * QS + 2 * BN * QS);

        if (nw == 1) {
            float* base = Osum + mw * 32 * OS;
            #pragma unroll
            for (int mi = 0; mi < 2; ++mi) {
                const int r0 = 16 * mi + grp;
                #pragma unroll
                for (int tn = 0; tn < 8; ++tn) {
                    *(float2*)(base + r0 * OS + 8 * tn + 2 * c) =
                        make_float2(oacc[mi][tn][0], oacc[mi][tn][1]);
                    *(float2*)(base + (r0 + 8) * OS + 8 * tn + 2 * c) =
                        make_float2(oacc[mi][tn][2], oacc[mi][tn][3]);
                }
                if (c == 0) {
                    Zsum[rbase + 16 * mi + grp]     = zr[mi][0];
                    Zsum[rbase + 16 * mi + grp + 8] = zr[mi][1];
                }
            }
        }
        __syncthreads();

        if (nw == 0) {
            float* base = Osum + mw * 32 * OS;
            #pragma unroll
            for (int mi = 0; mi < 2; ++mi) {
                const int r0 = 16 * mi + grp;
                const float z0 = zr[mi][0] + Zsum[rbase + r0];
                const float z1 = zr[mi][1] + Zsum[rbase + r0 + 8];
                const float inv0 = 1.0f / (z0 + 1e-6f);
                const float inv1 = 1.0f / (z1 + 1e-6f);
                float* ob0 = O + (size_t)bh * L_SEQ * DHEAD
                           + (size_t)(qbase + rbase + r0) * DHEAD + 2 * c;
                float* ob1 = ob0 + 8 * DHEAD;
                #pragma unroll
                for (int tn = 0; tn < 8; ++tn) {
                    const float2 s0 = *(const float2*)(base + r0 * OS + 8 * tn + 2 * c);
                    const float2 s1 = *(const float2*)(base + (r0 + 8) * OS + 8 * tn + 2 * c);
                    float2 w0, w1;
                    w0.x = (oacc[mi][tn][0] + s0.x) * inv0;
                    w0.y = (oacc[mi][tn][1] + s0.y) * inv0;
                    w1.x = (oacc[mi][tn][2] + s1.x) * inv1;
                    w1.y = (oacc[mi][tn][3] + s1.y) * inv1;
                    *(float2*)(ob0 + 8 * tn) = w0;
                    *(float2*)(ob1 + 8 * tn) = w1;
                }
            }
        }
        __syncthreads();   // Osum readers done before next tile's prologue
    }
}

extern "C" void kernel_launch(void* const* d_in, const int* in_sizes, int n_in,
                              void* d_out, int out_size) {
    (void)in_sizes; (void)n_in; (void)out_size;
    const float* q = (const float*)d_in[0];
    const float* k = (const float*)d_in[1];
    const float* v = (const float*)d_in[2];
    float* o = (float*)d_out;

    const int smem_bytes = SMEM_MAIN + 16;
    static bool configured = false;
    if (!configured) {
        cudaFuncSetAttribute(taylor_attn_h,
                             cudaFuncAttributeMaxDynamicSharedMemorySize, smem_bytes);
        configured = true;
    }

    prep_all<<<dim3(1024, 2), 256>>>(k, v);

    taylor_attn_h<<<304, 256, smem_bytes>>>(q, o);   // persistent: 2 CTAs x 152 SMs
}

// round 17
// speedup vs baseline: 1.2163x; 1.1800x over previous
#include <cuda_runtime.h>
#include <cuda_fp16.h>
#include <cstdint>

// Taylor causal attention, fp16 mma.sync m16n8k16 (fp32 accum).
// Small-CTA retile: BM=64, BN=64, 4 warps/CTA, 4 independent CTAs per SM
// (46 KB smem) so co-resident warps on an SMSP never share a barrier.
// Each warp owns 16 rows x full k-range -> no cross-warp O/z reduction.
// ldmatrix fragment loads; persistent CTAs + dynamic LPT queue.
// B=2,H=16,L=2048,D=64. Tile: 64 q-rows, k-tiles of 64.

#define L_SEQ 2048
#define DHEAD 64
#define NBH   32
#define BM    64
#define BN    64
#define QS    72     // Q/K smem row stride in halves (144B; ldmatrix conflict-free)
#define VTS   72     // Vt smem row stride in halves
#define NTILES 1024
#define SMEM_MAIN ((BM * QS + 2 * BN * QS + 2 * 64 * VTS) * 2)   // 46080 B

__device__ __align__(16) __half g_Kh[NBH * L_SEQ * DHEAD];  // row-major
__device__ __align__(16) __half g_Vth[NBH * DHEAD * L_SEQ]; // transposed [d][k]
__device__ int g_ctr;                                        // work-queue cursor

static __device__ __forceinline__ uint32_t packh2(float lo, float hi) {
    __half2 h = __floats2half2_rn(lo, hi);
    return *(uint32_t*)&h;
}
static __device__ __forceinline__ uint32_t smem_u32(const void* p) {
    uint32_t a;
    asm("{ .reg .u64 t; cvta.to.shared.u64 t, %1; cvt.u32.u64 %0, t; }" : "=r"(a) : "l"(p));
    return a;
}
static __device__ __forceinline__ void cp16(uint32_t s, const void* g) {
    asm volatile("cp.async.cg.shared.global [%0], [%1], 16;"
                 :: "r"(s), "l"(__cvta_generic_to_global(g)));
}
static __device__ __forceinline__ void cp_commit() {
    asm volatile("cp.async.commit_group;" ::: "memory");
}
static __device__ __forceinline__ void cp_wait0() {
    asm volatile("cp.async.wait_group 0;" ::: "memory");
}
static __device__ __forceinline__ void ldsm4(uint32_t& r0, uint32_t& r1,
                                             uint32_t& r2, uint32_t& r3, uint32_t a) {
    asm volatile("ldmatrix.sync.aligned.m8n8.x4.shared.b16 {%0,%1,%2,%3}, [%4];"
                 : "=r"(r0), "=r"(r1), "=r"(r2), "=r"(r3) : "r"(a));
}
static __device__ __forceinline__ void mma16(float* d,
        uint32_t a0, uint32_t a1, uint32_t a2, uint32_t a3,
        uint32_t b0, uint32_t b1) {
    asm volatile(
        "mma.sync.aligned.m16n8k16.row.col.f32.f16.f16.f32 "
        "{%0,%1,%2,%3}, {%4,%5,%6,%7}, {%8,%9}, {%0,%1,%2,%3};"
        : "+f"(d[0]), "+f"(d[1]), "+f"(d[2]), "+f"(d[3])
        : "r"(a0), "r"(a1), "r"(a2), "r"(a3), "r"(b0), "r"(b1));
}

// ---- prep: y=0 -> K fp16 convert (row-major); y=1 -> V transpose ----
__global__ void __launch_bounds__(256)
prep_all(const float* __restrict__ K, const float* __restrict__ V)
{
    if (blockIdx.x == 0 && blockIdx.y == 0 && threadIdx.x == 0) g_ctr = 0;

    if (blockIdx.y == 0) {
        const int g   = blockIdx.x * 256 + threadIdx.x;   // one (row, 16-col blk)
        const size_t off = (size_t)(g >> 2) * DHEAD + ((g & 3) << 4);

        float4 f0 = *(const float4*)(K + off);
        float4 f1 = *(const float4*)(K + off + 4);
        float4 f2 = *(const float4*)(K + off + 8);
        float4 f3 = *(const float4*)(K + off + 12);
        uint4 a, b;
        a.x = packh2(f0.x, f0.y);  a.y = packh2(f0.z, f0.w);
        a.z = packh2(f1.x, f1.y);  a.w = packh2(f1.z, f1.w);
        b.x = packh2(f2.x, f2.y);  b.y = packh2(f2.z, f2.w);
        b.z = packh2(f3.x, f3.y);  b.w = packh2(f3.z, f3.w);
        *(uint4*)(g_Kh + off)     = a;
        *(uint4*)(g_Kh + off + 8) = b;
    } else {
        __shared__ float ts[64][68];
        const int tid = threadIdx.x;
        const int kt0 = (blockIdx.x & 31) * 64;
        const int bh  = blockIdx.x >> 5;
        const float* vsrc = V + (size_t)bh * L_SEQ * DHEAD;
        __half* vdst = g_Vth + (size_t)bh * DHEAD * L_SEQ;

        #pragma unroll
        for (int i = 0; i < 4; ++i) {
            const int idx = tid + 256 * i;
            const int row = idx >> 4, c4 = (idx & 15) << 2;
            *(float4*)&ts[row][c4] =
                *(const float4*)(vsrc + (size_t)(kt0 + row) * DHEAD + c4);
        }
        __syncthreads();

        const int d  = tid >> 2;
        const int kb = (tid & 3) << 4;
        uint4 a, b;
        a.x = packh2(ts[kb + 0][d],  ts[kb + 1][d]);
        a.y = packh2(ts[kb + 2][d],  ts[kb + 3][d]);
        a.z = packh2(ts[kb + 4][d],  ts[kb + 5][d]);
        a.w = packh2(ts[kb + 6][d],  ts[kb + 7][d]);
        b.x = packh2(ts[kb + 8][d],  ts[kb + 9][d]);
        b.y = packh2(ts[kb + 10][d], ts[kb + 11][d]);
        b.z = packh2(ts[kb + 12][d], ts[kb + 13][d]);
        b.w = packh2(ts[kb + 14][d], ts[kb + 15][d]);
        __half* dst = vdst + (size_t)d * L_SEQ + kt0 + kb;
        *(uint4*)dst       = a;
        *(uint4*)(dst + 8) = b;
    }
}

// ---- one k-tile (4 chunks of 16 cols) for one warp (16 rows x 64 cols) ----
template<bool DIAG>
static __device__ __forceinline__ void tile_step(
    uint32_t kBase, uint32_t vBase,
    const uint32_t (&qf)[4][4],
    float (&oacc)[8][4], float (&zr)[2],
    int rbase, int c)
{
    #pragma unroll
    for (int ch = 0; ch < 4; ++ch) {
        const int cb0 = 16 * ch;                  // chunk column base (local)
        if (DIAG && cb0 > rbase + 15) break;      // fully above all warp rows
        const bool t1 = !DIAG || (cb0 + 8 <= rbase + 15);

        // ---- MMA1: S chunk (16 rows x 16 cols); K frags via ldmatrix ----
        float sacc[2][4];
        #pragma unroll
        for (int t = 0; t < 2; ++t)
            #pragma unroll
            for (int jj = 0; jj < 4; ++jj) sacc[t][jj] = 0.0f;

        const uint32_t kCh = kBase + (uint32_t)(cb0 * QS) * 2;
        #pragma unroll
        for (int s = 0; s < 4; ++s) {
            uint32_t k0, k1, k2, k3;
            ldsm4(k0, k1, k2, k3, kCh + 32u * s);
            mma16(sacc[0], qf[s][0], qf[s][1], qf[s][2], qf[s][3], k0, k1);
            if (t1)
                mma16(sacc[1], qf[s][0], qf[s][1], qf[s][2], qf[s][3], k2, k3);
        }

        // ---- epilogue: f(s), mask, z, pack ----
        uint32_t pr[2][2];
        #pragma unroll
        for (int t = 0; t < 2; ++t) { pr[t][0] = 0u; pr[t][1] = 0u; }
        const int r0 = rbase + ((threadIdx.x & 31) >> 2);
        #pragma unroll
        for (int t = 0; t < 2; ++t) {
            if (DIAG && t == 1 && !t1) continue;
            const int cb = cb0 + 8 * t + 2 * c;   // local col of p0/p2
            float s0 = sacc[t][0], s1 = sacc[t][1];
            float s2 = sacc[t][2], s3 = sacc[t][3];
            float p0 = fmaf(fmaf(0.5f, s0, 1.0f), s0, 1.0f);
            float p1 = fmaf(fmaf(0.5f, s1, 1.0f), s1, 1.0f);
            float p2 = fmaf(fmaf(0.5f, s2, 1.0f), s2, 1.0f);
            float p3 = fmaf(fmaf(0.5f, s3, 1.0f), s3, 1.0f);
            if (DIAG) {
                if (cb     > r0)     p0 = 0.0f;
                if (cb + 1 > r0)     p1 = 0.0f;
                if (cb     > r0 + 8) p2 = 0.0f;
                if (cb + 1 > r0 + 8) p3 = 0.0f;
            }
            zr[0] += p0 + p1;
            zr[1] += p2 + p3;
            pr[t][0] = packh2(p0, p1);
            pr[t][1] = packh2(p2, p3);
        }

        // ---- MMA2: O += P @ V ; V frags via ldmatrix; A-frag = pr in-lane ----
        const uint32_t vCh = vBase + (uint32_t)cb0 * 2;
        #pragma unroll
        for (int tp = 0; tp < 4; ++tp) {
            uint32_t v0, v1, v2, v3;
            ldsm4(v0, v1, v2, v3, vCh + (uint32_t)(32 * VTS) * tp);
            mma16(oacc[2 * tp],     pr[0][0], pr[0][1], pr[1][0], pr[1][1], v0, v1);
            mma16(oacc[2 * tp + 1], pr[0][0], pr[0][1], pr[1][0], pr[1][1], v2, v3);
        }
    }
}

// ---- main kernel: persistent small CTAs over a dynamic LPT work list ----
__global__ void __launch_bounds__(128, 4)
taylor_attn_h(const float* __restrict__ Q, float* __restrict__ O)
{
    extern __shared__ __half smh[];
    __half* Qs = smh;                      // [64][72]
    __half* Kb = Qs + BM * QS;             // [2][64][72]
    __half* Vb = Kb + 2 * BN * QS;         // [2][64][72]
    int* wptr  = (int*)((char*)smh + SMEM_MAIN);
    const uint32_t sKb = smem_u32(Kb);
    const uint32_t sVb = smem_u32(Vb);
    const uint32_t sQs = smem_u32(Qs);

    const int tid  = threadIdx.x;
    const int wid  = tid >> 5;             // 0..3: row group (16 rows each)
    const int lane = tid & 31;
    const int grp  = lane >> 2;
    const int c    = lane & 3;
    const int rbase = 16 * wid;

    // per-lane ldmatrix offsets (halves)
    const int lo8 = lane & 7;
    const int selA = (lane >> 3) & 1;
    const int selB = (lane >> 4) & 1;
    const int kLane = (selB * 8 + lo8) * QS + selA * 8;
    const int vLane = (selB * 8 + lo8) * VTS + selA * 8;
    const int qLane = (selA * 8 + lo8) * QS + selB * 8;
    const uint32_t qAddr = sQs + (uint32_t)(qLane + rbase * QS) * 2;

    for (;;) {
        if (tid == 0) *wptr = atomicAdd(&g_ctr, 1);
        __syncthreads();
        const int widx = *wptr;
        if (widx >= NTILES) break;

        const int qt = (L_SEQ / BM) - 1 - (widx >> 5);   // LPT: big first
        const int bh = widx & 31;
        const int qbase = qt * BM;

        const float*  Qg = Q + (size_t)bh * L_SEQ * DHEAD + (size_t)qbase * DHEAD;
        const __half* Kg = g_Kh + (size_t)bh * L_SEQ * DHEAD;
        const __half* Vg = g_Vth + (size_t)bh * DHEAD * L_SEQ;

        // ---- prologue: K/V tile 0 via cp.async; Q fp32 -> fp16 convert ----
        #pragma unroll
        for (int i = 0; i < 4; ++i) {
            const int idx = tid + 128 * i;
            const int row = idx >> 3, ch = idx & 7;
            cp16(sKb + (uint32_t)(row * QS + ch * 8) * 2,
                 Kg + (size_t)row * DHEAD + ch * 8);
            cp16(sVb + (uint32_t)(row * VTS + ch * 8) * 2,
                 Vg + (size_t)row * L_SEQ + ch * 8);
        }
        cp_commit();

        // Q: 256 items of 16 floats each -> 16 halves (scaled by 1/8)
        #pragma unroll
        for (int i = 0; i < 2; ++i) {
            const int item = tid + 128 * i;
            const int row  = item >> 2;
            const int c16  = (item & 3) << 4;
            const float* src = Qg + (size_t)row * DHEAD + c16;
            float4 f0 = *(const float4*)(src);
            float4 f1 = *(const float4*)(src + 4);
            float4 f2 = *(const float4*)(src + 8);
            float4 f3 = *(const float4*)(src + 12);
            uint4 a, b;
            a.x = packh2(f0.x * 0.125f, f0.y * 0.125f);
            a.y = packh2(f0.z * 0.125f, f0.w * 0.125f);
            a.z = packh2(f1.x * 0.125f, f1.y * 0.125f);
            a.w = packh2(f1.z * 0.125f, f1.w * 0.125f);
            b.x = packh2(f2.x * 0.125f, f2.y * 0.125f);
            b.y = packh2(f2.z * 0.125f, f2.w * 0.125f);
            b.z = packh2(f3.x * 0.125f, f3.y * 0.125f);
            b.w = packh2(f3.z * 0.125f, f3.w * 0.125f);
            *(uint4*)(Qs + row * QS + c16)     = a;
            *(uint4*)(Qs + row * QS + c16 + 8) = b;
        }
        cp_wait0();
        __syncthreads();

        // ---- Q fragments -> registers for the whole k-loop (ldmatrix) ----
        uint32_t qf[4][4];
        #pragma unroll
        for (int s = 0; s < 4; ++s)
            ldsm4(qf[s][0], qf[s][1], qf[s][2], qf[s][3], qAddr + 32u * s);

        float oacc[8][4];
        #pragma unroll
        for (int t = 0; t < 8; ++t)
            #pragma unroll
            for (int j = 0; j < 4; ++j) oacc[t][j] = 0.0f;
        float zr[2] = {};

        for (int j = 0; j <= qt; ++j) {
            const int buf = j & 1;

            if (j < qt) {   // prefetch tile j+1 into the other buffer
                const int nb = buf ^ 1;
                const int kb1 = (j + 1) * BN;
                const uint32_t dK = sKb + (uint32_t)(nb * BN * QS) * 2;
                const uint32_t dV = sVb + (uint32_t)(nb * 64 * VTS) * 2;
                #pragma unroll
                for (int i = 0; i < 4; ++i) {
                    const int idx = tid + 128 * i;
                    const int row = idx >> 3, ch = idx & 7;
                    cp16(dK + (uint32_t)(row * QS + ch * 8) * 2,
                         Kg + (size_t)(kb1 + row) * DHEAD + ch * 8);
                    cp16(dV + (uint32_t)(row * VTS + ch * 8) * 2,
                         Vg + (size_t)row * L_SEQ + kb1 + ch * 8);
                }
                cp_commit();
            }

            const uint32_t kBase = sKb + (uint32_t)(buf * BN * QS) * 2
                                 + (uint32_t)kLane * 2;
            const uint32_t vBase = sVb + (uint32_t)(buf * 64 * VTS) * 2
                                 + (uint32_t)vLane * 2;
            if (j == qt)
                tile_step<true >(kBase, vBase, qf, oacc, zr, rbase, c);
            else
                tile_step<false>(kBase, vBase, qf, oacc, zr, rbase, c);

            if (j < qt) cp_wait0();
            __syncthreads();   // buf free + next tile visible to all warps
        }

        // ---- z lane-reduce over the 4 c-lanes; direct store ----
        zr[0] += __shfl_xor_sync(0xffffffffu, zr[0], 1);
        zr[0] += __shfl_xor_sync(0xffffffffu, zr[0], 2);
        zr[1] += __shfl_xor_sync(0xffffffffu, zr[1], 1);
        zr[1] += __shfl_xor_sync(0xffffffffu, zr[1], 2);
        const float inv0 = 1.0f / (zr[0] + 1e-6f);
        const float inv1 = 1.0f / (zr[1] + 1e-6f);

        float* ob0 = O + (size_t)bh * L_SEQ * DHEAD
                   + (size_t)(qbase + rbase + grp) * DHEAD + 2 * c;
        float* ob1 = ob0 + 8 * DHEAD;
        #pragma unroll
        for (int tn = 0; tn < 8; ++tn) {
            float2 w0; w0.x = oacc[tn][0] * inv0; w0.y = oacc[tn][1] * inv0;
            float2 w1; w1.x = oacc[tn][2] * inv1; w1.y = oacc[tn][3] * inv1;
            *(float2*)(ob0 + 8 * tn) = w0;
            *(float2*)(ob1 + 8 * tn) = w1;
        }
    }
}

extern "C" void kernel_launch(void* const* d_in, const int* in_sizes, int n_in,
                              void* d_out, int out_size) {
    (void)in_sizes; (void)n_in; (void)out_size;
    const float* q = (const float*)d_in[0];
    const float* k = (const float*)d_in[1];
    const float* v = (const float*)d_in[2];
    float* o = (float*)d_out;

    const int smem_bytes = SMEM_MAIN + 16;   // + work-index broadcast slot
    static bool configured = false;
    if (!configured) {
        cudaFuncSetAttribute(taylor_attn_h,
                             cudaFuncAttributeMaxDynamicSharedMemorySize, smem_bytes);
        configured = true;
    }

    prep_all<<<dim3(1024, 2), 256>>>(k, v);

    taylor_attn_h<<<608, 128, smem_bytes>>>(q, o);   // persistent: 4 CTAs x 152 SMs
}